// round 6
// baseline (speedup 1.0000x reference)
#include <cuda_runtime.h>
#include <stdint.h>

#define N_TOK   32768
#define N_CODE  8192
#define DIM     256
#define QUANT_ELEMS (N_TOK * DIM)

// ---------------- static scratch ----------------
// Fragment-packed 3-way tf32 split (m16n8k8 register order).
// g_xs: [blk16 (2048)][kstep (32)][part (3)][lane (32)][e (4)]   ~100.7 MB
// g_es: [blk8  (1024)][kstep (32)][part (3)][lane (32)][e (2)]   ~25.2 MB
__device__ float g_xs[(size_t)2048 * 32 * 3 * 128];
__device__ float g_es[(size_t)1024 * 32 * 3 * 64];
__device__ float g_e2[N_CODE];
__device__ int   g_idx[N_TOK];
__device__ float g_part[4096];

// ---------------- helpers ----------------
__device__ __forceinline__ uint32_t smem_u32(const void* p) {
    uint32_t a;
    asm("{ .reg .u64 t; cvta.to.shared.u64 t, %1; cvt.u32.u64 %0, t; }"
        : "=r"(a) : "l"(p));
    return a;
}
__device__ __forceinline__ void cp16(uint32_t dst, const void* src) {
    asm volatile("cp.async.cg.shared.global [%0], [%1], 16;" :: "r"(dst), "l"(src));
}
#define CP_COMMIT() asm volatile("cp.async.commit_group;" ::: "memory")
#define CP_WAIT(n)  asm volatile("cp.async.wait_group %0;" :: "n"(n) : "memory")

// exact 3-way tf32 split: x == h + m + l (fp32 subtractions are exact)
__device__ __forceinline__ void split3(float x, float& h, float& m, float& l) {
    uint32_t b;
    asm("cvt.rna.tf32.f32 %0, %1;" : "=r"(b) : "f"(x));
    h = __uint_as_float(b);
    float r1 = x - h;
    asm("cvt.rna.tf32.f32 %0, %1;" : "=r"(b) : "f"(r1));
    m = __uint_as_float(b);
    float r2 = r1 - m;
    asm("cvt.rna.tf32.f32 %0, %1;" : "=r"(b) : "f"(r2));
    l = __uint_as_float(b);
}

// m16n8k8 tf32 mma, D += A*B (row.col), accumulate in place
__device__ __forceinline__ void mma8(float* c, const float4& a, const float2& b) {
    asm volatile(
        "mma.sync.aligned.m16n8k8.row.col.f32.tf32.tf32.f32 "
        "{%0,%1,%2,%3}, {%4,%5,%6,%7}, {%8,%9}, {%0,%1,%2,%3};"
        : "+f"(c[0]), "+f"(c[1]), "+f"(c[2]), "+f"(c[3])
        : "r"(__float_as_uint(a.x)), "r"(__float_as_uint(a.y)),
          "r"(__float_as_uint(a.z)), "r"(__float_as_uint(a.w)),
          "r"(__float_as_uint(b.x)), "r"(__float_as_uint(b.y)));
}

// ---------------- prep kernels ----------------
__global__ void k_prep_x(const float* __restrict__ X) {
    int gt   = blockIdx.x * 256 + threadIdx.x;   // 2,097,152 threads
    int lane = gt & 31;
    int w    = gt >> 5;
    int s    = w & 31;           // kstep
    int blk  = w >> 5;           // token block of 16
    int g = lane >> 2, t = lane & 3;
    float h[4], m[4], l[4];
#pragma unroll
    for (int e = 0; e < 4; e++) {
        int tok = blk * 16 + g + (e & 1) * 8;
        int k   = s * 8 + t + (e >> 1) * 4;
        split3(X[tok * DIM + k], h[e], m[e], l[e]);
    }
    float* base = g_xs + ((size_t)(blk * 32 + s) * 3) * 128 + lane * 4;
    *(float4*)(base)       = make_float4(h[0], h[1], h[2], h[3]);
    *(float4*)(base + 128) = make_float4(m[0], m[1], m[2], m[3]);
    *(float4*)(base + 256) = make_float4(l[0], l[1], l[2], l[3]);
}

__global__ void k_prep_e(const float* __restrict__ E) {
    int gt   = blockIdx.x * 256 + threadIdx.x;   // 1,048,576 threads
    int lane = gt & 31;
    int w    = gt >> 5;
    int s    = w & 31;
    int blk  = w >> 5;           // code block of 8
    int g = lane >> 2, t = lane & 3;
    float h[2], m[2], l[2];
#pragma unroll
    for (int e = 0; e < 2; e++) {
        int code = blk * 8 + g;
        int k    = s * 8 + t + e * 4;
        split3(E[code * DIM + k], h[e], m[e], l[e]);
    }
    float* base = g_es + ((size_t)(blk * 32 + s) * 3) * 64 + lane * 2;
    *(float2*)(base)       = make_float2(h[0], h[1]);
    *(float2*)(base + 64)  = make_float2(m[0], m[1]);
    *(float2*)(base + 128) = make_float2(l[0], l[1]);
}

__global__ void k_e2(const float* __restrict__ E) {
    int warp = (blockIdx.x << 3) + (threadIdx.x >> 5);
    int lane = threadIdx.x & 31;
    const float* row = E + warp * DIM;
    float s = 0.f;
#pragma unroll
    for (int i = 0; i < 8; i++) { float v = row[lane + i * 32]; s = fmaf(v, v, s); }
#pragma unroll
    for (int off = 16; off; off >>= 1) s += __shfl_down_sync(0xffffffffu, s, off);
    if (lane == 0) g_e2[warp] = s;
}

// ---------------- main: tf32 6-pass mma.sync GEMM + fused argmin ----------------
// 256 CTAs x 256 threads (2 m-warps x 4 n-warps, warp tile 64x32).
// CTA tile: 128 tokens x 128 codes; BK=16 (2 ksteps), double-buffered cp.async.
#define STAGE_BYTES 49152          // A 24576 + B 24576

__global__ __launch_bounds__(256, 2) void k_main(float* __restrict__ out_idx_f) {
    extern __shared__ __align__(16) char sm[];
    __shared__ unsigned long long s_min[128];

    const int tid  = threadIdx.x;
    const int lane = tid & 31, wid = tid >> 5;
    const int wm = wid & 1, wn = wid >> 1;      // 2 x 4 warp grid
    const int g = lane >> 2, t = lane & 3;
    const int m0 = blockIdx.x * 128;
    const uint32_t sb = smem_u32(sm);

    if (tid < 128) s_min[tid] = ~0ull;

    const char* gA = (const char*)g_xs + (size_t)blockIdx.x * 8 * 49152;
    const char* gE = (const char*)g_es;

    // prologue: chunk 0 -> stage 0
#pragma unroll
    for (int i = 0; i < 6; i++) {
        int idx = tid + i * 256;
        int mblk = idx / 192, off = (idx % 192) * 16;
        cp16(sb + mblk * 3072 + off, gA + (size_t)mblk * 49152 + off);
    }
#pragma unroll
    for (int i = 0; i < 6; i++) {
        int idx = tid + i * 256;
        int nblk = idx / 96, off = (idx % 96) * 16;
        cp16(sb + 24576 + nblk * 1536 + off, gE + (size_t)nblk * 24576 + off);
    }
    CP_COMMIT();

    float cacc[4][4][4];
    float minv[8];
    int   mini[8];
#pragma unroll
    for (int i = 0; i < 8; i++) { minv[i] = 3.4e38f; mini[i] = 0; }

    for (int c = 0; c < 1024; c++) {           // 64 n-tiles x 16 chunks
        const int nt = c >> 4, kc = c & 15, s = c & 1;
        const char* smA = sm + s * STAGE_BYTES;
        const char* smB = smA + 24576;

        // issue chunk c+1 into the other stage
        if (c + 1 < 1024) {
            const int c2 = c + 1, nt2 = c2 >> 4, kc2 = c2 & 15, s2 = c2 & 1;
            const uint32_t dA = sb + s2 * STAGE_BYTES, dB = dA + 24576;
            const char* srcA = gA + kc2 * 3072;
            const char* srcB = gE + (size_t)nt2 * 16 * 24576 + kc2 * 1536;
#pragma unroll
            for (int i = 0; i < 6; i++) {
                int idx = tid + i * 256;
                int mblk = idx / 192, off = (idx % 192) * 16;
                cp16(dA + mblk * 3072 + off, srcA + (size_t)mblk * 49152 + off);
            }
#pragma unroll
            for (int i = 0; i < 6; i++) {
                int idx = tid + i * 256;
                int nblk = idx / 96, off = (idx % 96) * 16;
                cp16(dB + nblk * 1536 + off, srcB + (size_t)nblk * 24576 + off);
            }
            CP_COMMIT();
            CP_WAIT(1);                        // chunk c landed
        } else {
            CP_WAIT(0);
        }
        __syncthreads();

        if (kc == 0) {
#pragma unroll
            for (int mf = 0; mf < 4; mf++)
#pragma unroll
                for (int nf = 0; nf < 4; nf++)
#pragma unroll
                    for (int e = 0; e < 4; e++) cacc[mf][nf][e] = 0.f;
        }

        // 6-pass tf32 mma over 2 ksteps: pairs (ap,bp) with ap+bp <= 2
#pragma unroll
        for (int ks = 0; ks < 2; ks++) {
#pragma unroll
            for (int ap = 0; ap < 3; ap++) {
                float4 af[4];
#pragma unroll
                for (int mf = 0; mf < 4; mf++)
                    af[mf] = *(const float4*)(smA + (wm * 4 + mf) * 3072 +
                                              (ks * 3 + ap) * 512 + lane * 16);
#pragma unroll
                for (int bp = 0; bp < 3; bp++) {
                    if (bp < 3 - ap) {
#pragma unroll
                        for (int nf = 0; nf < 4; nf++) {
                            float2 bf = *(const float2*)(smB + (wn * 4 + nf) * 1536 +
                                                         (ks * 3 + bp) * 256 + lane * 8);
#pragma unroll
                            for (int mf = 0; mf < 4; mf++)
                                mma8(cacc[mf][nf], af[mf], bf);
                        }
                    }
                }
            }
        }

        if (kc == 15) {
            // distances + running per-thread argmin (codes ascend => first-min kept)
            const float* e2t = g_e2 + nt * 128 + wn * 32;
#pragma unroll
            for (int nf = 0; nf < 4; nf++) {
                float2 e2v = *(const float2*)(e2t + nf * 8 + 2 * t);
                int code = nt * 128 + wn * 32 + nf * 8 + 2 * t;
#pragma unroll
                for (int mf = 0; mf < 4; mf++) {
#pragma unroll
                    for (int h = 0; h < 2; h++) {
                        int tk = mf * 2 + h;
                        float d0 = fmaf(-2.f, cacc[mf][nf][h * 2 + 0], e2v.x);
                        float d1 = fmaf(-2.f, cacc[mf][nf][h * 2 + 1], e2v.y);
                        if (d0 < minv[tk]) { minv[tk] = d0; mini[tk] = code; }
                        if (d1 < minv[tk]) { minv[tk] = d1; mini[tk] = code + 1; }
                    }
                }
            }
        }
        __syncthreads();
    }

    // merge: quad shfl (codes dim) then packed atomicMin (dist-ordered | code)
#pragma unroll
    for (int tk = 0; tk < 8; tk++) {
        uint32_t u = __float_as_uint(minv[tk]);
        u = (u & 0x80000000u) ? ~u : (u | 0x80000000u);
        unsigned long long p = ((unsigned long long)u << 32) | (unsigned)mini[tk];
        unsigned long long q;
        q = __shfl_xor_sync(0xffffffffu, p, 1); if (q < p) p = q;
        q = __shfl_xor_sync(0xffffffffu, p, 2); if (q < p) p = q;
        if (t == 0) {
            int mf = tk >> 1, h = tk & 1;
            atomicMin(&s_min[wm * 64 + mf * 16 + g + h * 8], p);
        }
    }
    __syncthreads();
    if (tid < 128) {
        int idx = (int)(s_min[tid] & 0xffffffffu);
        g_idx[m0 + tid]     = idx;
        out_idx_f[m0 + tid] = (float)idx;
    }
}

// ---------------- gather + loss (proven in round 3) ----------------
__global__ void k_gather(const float* __restrict__ X, const float* __restrict__ E,
                         float* __restrict__ outq) {
    __shared__ float red[256];
    const int tid = threadIdx.x;
    const long base = (long)blockIdx.x * 2048;
    float s = 0.f;
#pragma unroll
    for (int i = 0; i < 8; i++) {
        long e = base + i * 256 + tid;
        int  m = (int)(e >> 8);
        int  d = (int)(e & 255);
        float q = E[g_idx[m] * DIM + d];
        float x = X[e];
        float diff = q - x;
        outq[e] = x + diff;
        s = fmaf(diff, diff, s);
    }
    red[tid] = s;
    __syncthreads();
#pragma unroll
    for (int st = 128; st; st >>= 1) {
        if (tid < st) red[tid] += red[tid + st];
        __syncthreads();
    }
    if (tid == 0) g_part[blockIdx.x] = red[0];
}
__global__ void k_loss(float* __restrict__ loss_out) {
    __shared__ float red[256];
    const int tid = threadIdx.x;
    float s = 0.f;
    for (int i = tid; i < 4096; i += 256) s += g_part[i];
    red[tid] = s;
    __syncthreads();
#pragma unroll
    for (int st = 128; st; st >>= 1) {
        if (tid < st) red[tid] += red[tid + st];
        __syncthreads();
    }
    if (tid == 0) loss_out[0] = 2.0f * (red[0] / (float)QUANT_ELEMS);
}

// ---------------- launch ----------------
extern "C" void kernel_launch(void* const* d_in, const int* in_sizes, int n_in,
                              void* d_out, int out_size) {
    const float* X = (const float*)d_in[0];
    const float* E = (const float*)d_in[1];
    float* out = (float*)d_out;

    float* outq    = out;
    float* outloss = out + QUANT_ELEMS;
    float* outidx  = out + QUANT_ELEMS + 1;

    cudaFuncSetAttribute(k_main, cudaFuncAttributeMaxDynamicSharedMemorySize,
                         2 * STAGE_BYTES);

    k_prep_x<<<8192, 256>>>(X);
    k_prep_e<<<4096, 256>>>(E);
    k_e2    <<<N_CODE / 8, 256>>>(E);
    k_main  <<<N_TOK / 128, 256, 2 * STAGE_BYTES>>>(outidx);
    k_gather<<<QUANT_ELEMS / 2048, 256>>>(X, E, outq);
    k_loss  <<<1, 256>>>(outloss);

    (void)in_sizes; (void)n_in; (void)out_size;
}

// round 7
// speedup vs baseline: 1.9932x; 1.9932x over previous
#include <cuda_runtime.h>
#include <cuda_bf16.h>
#include <stdint.h>

#define N_TOK   32768
#define N_CODE  8192
#define DIM     256
#define QUANT_ELEMS (N_TOK * DIM)

// ---------------- static scratch ----------------
// bf16 3-limb fragment-packed operands (m16n8k16 register order).
// g_xs: [blk16 (2048)][kstep (16)][limb (3)][lane (32)][4 x b32]  = 50.3 MB
// g_es: [blk8  (1024)][kstep (16)][limb (3)][lane (32)][2 x b32]  = 12.6 MB
__device__ uint32_t g_xs[(size_t)2048 * 16 * 3 * 128];
__device__ uint32_t g_es[(size_t)1024 * 16 * 3 * 64];
__device__ float g_e2[N_CODE];
__device__ int   g_idx[N_TOK];
__device__ float g_part[4096];

// ---------------- helpers ----------------
__device__ __forceinline__ uint32_t smem_u32(const void* p) {
    uint32_t a;
    asm("{ .reg .u64 t; cvta.to.shared.u64 t, %1; cvt.u32.u64 %0, t; }"
        : "=r"(a) : "l"(p));
    return a;
}
__device__ __forceinline__ void cp16(uint32_t dst, const void* src) {
    asm volatile("cp.async.cg.shared.global [%0], [%1], 16;" :: "r"(dst), "l"(src));
}
#define CP_COMMIT() asm volatile("cp.async.commit_group;" ::: "memory")
#define CP_WAIT(n)  asm volatile("cp.async.wait_group %0;" :: "n"(n) : "memory")

// exact 3-limb bf16 split: x = h + m + l + O(2^-24 x); subtractions exact
__device__ __forceinline__ void split3b(float x, float& h, float& m, float& l) {
    h = __bfloat162float(__float2bfloat16(x));
    float r1 = x - h;
    m = __bfloat162float(__float2bfloat16(r1));
    float r2 = r1 - m;
    l = __bfloat162float(__float2bfloat16(r2));
}
// pack two exact-bf16 floats into one b32 (lo in low half)
__device__ __forceinline__ uint32_t bpack(float lo, float hi) {
    return (__float_as_uint(hi) & 0xFFFF0000u) | (__float_as_uint(lo) >> 16);
}

// m16n8k16 bf16 mma, D += A*B (row.col), fp32 accumulate in place
__device__ __forceinline__ void mma16(float* c, const uint4& a, const uint2& b) {
    asm volatile(
        "mma.sync.aligned.m16n8k16.row.col.f32.bf16.bf16.f32 "
        "{%0,%1,%2,%3}, {%4,%5,%6,%7}, {%8,%9}, {%0,%1,%2,%3};"
        : "+f"(c[0]), "+f"(c[1]), "+f"(c[2]), "+f"(c[3])
        : "r"(a.x), "r"(a.y), "r"(a.z), "r"(a.w), "r"(b.x), "r"(b.y));
}

// ---------------- prep kernels ----------------
// A fragments: a0=(g,2t|2t+1) a1=(g+8,..) a2=(g,2t+8|2t+9) a3=(g+8,..)
__global__ void k_prep_x(const float* __restrict__ X) {
    int gt   = blockIdx.x * 256 + threadIdx.x;   // 1,048,576 threads
    int lane = gt & 31;
    int w    = gt >> 5;
    int ks   = w & 15;
    int blk  = w >> 4;                            // token block of 16
    int g = lane >> 2, t = lane & 3;
    const float* r0 = X + (blk * 16 + g) * DIM + ks * 16 + 2 * t;
    const float* r1 = r0 + 8 * DIM;
    float s[8] = { r0[0], r0[1], r1[0], r1[1], r0[8], r0[9], r1[8], r1[9] };
    float h[8], m[8], l[8];
#pragma unroll
    for (int i = 0; i < 8; i++) split3b(s[i], h[i], m[i], l[i]);
    uint32_t* base = g_xs + (size_t)(blk * 16 + ks) * 384 + lane * 4;
    *(uint4*)(base)       = make_uint4(bpack(h[0],h[1]), bpack(h[2],h[3]),
                                       bpack(h[4],h[5]), bpack(h[6],h[7]));
    *(uint4*)(base + 128) = make_uint4(bpack(m[0],m[1]), bpack(m[2],m[3]),
                                       bpack(m[4],m[5]), bpack(m[6],m[7]));
    *(uint4*)(base + 256) = make_uint4(bpack(l[0],l[1]), bpack(l[2],l[3]),
                                       bpack(l[4],l[5]), bpack(l[6],l[7]));
}

// B fragments: b0=(k=2t|2t+1, n=g), b1=(k=2t+8|2t+9, n=g)
__global__ void k_prep_e(const float* __restrict__ E) {
    int gt   = blockIdx.x * 256 + threadIdx.x;   // 524,288 threads
    int lane = gt & 31;
    int w    = gt >> 5;
    int ks   = w & 15;
    int blk  = w >> 4;                            // code block of 8
    int g = lane >> 2, t = lane & 3;
    const float* r = E + (blk * 8 + g) * DIM + ks * 16 + 2 * t;
    float s[4] = { r[0], r[1], r[8], r[9] };
    float h[4], m[4], l[4];
#pragma unroll
    for (int i = 0; i < 4; i++) split3b(s[i], h[i], m[i], l[i]);
    uint32_t* base = g_es + (size_t)(blk * 16 + ks) * 192 + lane * 2;
    *(uint2*)(base)       = make_uint2(bpack(h[0],h[1]), bpack(h[2],h[3]));
    *(uint2*)(base + 64)  = make_uint2(bpack(m[0],m[1]), bpack(m[2],m[3]));
    *(uint2*)(base + 128) = make_uint2(bpack(l[0],l[1]), bpack(l[2],l[3]));
}

__global__ void k_e2(const float* __restrict__ E) {
    int warp = (blockIdx.x << 3) + (threadIdx.x >> 5);
    int lane = threadIdx.x & 31;
    const float* row = E + warp * DIM;
    float s = 0.f;
#pragma unroll
    for (int i = 0; i < 8; i++) { float v = row[lane + i * 32]; s = fmaf(v, v, s); }
#pragma unroll
    for (int off = 16; off; off >>= 1) s += __shfl_down_sync(0xffffffffu, s, off);
    if (lane == 0) g_e2[warp] = s;
}

// ---------------- main: bf16 6-pass mma GEMM, A resident, fused argmin ------
// 256 CTAs x 256 threads (2 m-warps x 4 n-warps, warp tile 64x32).
// A slab (128 tok, all K, 3 limbs = 192 KB) resident; B streamed 12 KB chunks.
#define A_BYTES   196608
#define B_CHUNK   12288
#define SM_B0     A_BYTES
#define SM_B1     (A_BYTES + B_CHUNK)
#define SM_SMIN   (A_BYTES + 2 * B_CHUNK)
#define SM_TOTAL  (SM_SMIN + 1024)

__global__ __launch_bounds__(256, 1) void k_main(float* __restrict__ out_idx_f) {
    extern __shared__ __align__(16) char sm[];
    unsigned long long* s_min = (unsigned long long*)(sm + SM_SMIN);

    const int tid  = threadIdx.x;
    const int lane = tid & 31, wid = tid >> 5;
    const int wm = wid & 1, wn = wid >> 1;
    const int g = lane >> 2, t = lane & 3;
    const int m0 = blockIdx.x * 128;
    const uint32_t sb = smem_u32(sm);

    if (tid < 128) s_min[tid] = ~0ull;

    const char* gA = (const char*)g_xs + (size_t)blockIdx.x * A_BYTES;
    const char* gE = (const char*)g_es;

    // A slab: one-shot load (group 1)
#pragma unroll
    for (int i = 0; i < 48; i++) {
        int off = (tid + i * 256) * 16;
        cp16(sb + off, gA + off);
    }
    CP_COMMIT();
    // B chunk 0 (nt=0, ks=0) -> stage 0 (group 2)
#pragma unroll
    for (int i = 0; i < 3; i++) {
        int idx = tid + i * 256;
        int j = idx / 48, inner = (idx % 48) * 16;
        cp16(sb + SM_B0 + j * 768 + inner, gE + (size_t)j * 12288 + inner);
    }
    CP_COMMIT();

    float cacc[4][4][4];
    float minv[8];
    int   mini[8];
#pragma unroll
    for (int i = 0; i < 8; i++) { minv[i] = 3.4e38f; mini[i] = 0; }

    for (int c = 0; c < 1024; c++) {            // 64 n-tiles x 16 ksteps
        const int nt = c >> 4, ks = c & 15, s = c & 1;

        if (c + 1 < 1024) {                      // prefetch chunk c+1
            const int c2 = c + 1, nt2 = c2 >> 4, ks2 = c2 & 15;
            const uint32_t dst = sb + ((c2 & 1) ? SM_B1 : SM_B0);
            const char* src = gE + (size_t)nt2 * 16 * 12288 + ks2 * 768;
#pragma unroll
            for (int i = 0; i < 3; i++) {
                int idx = tid + i * 256;
                int j = idx / 48, inner = (idx % 48) * 16;
                cp16(dst + j * 768 + inner, src + (size_t)j * 12288 + inner);
            }
            CP_COMMIT();
            CP_WAIT(1);                          // chunk c (and A) landed
        } else {
            CP_WAIT(0);
        }
        __syncthreads();

        if (ks == 0) {
#pragma unroll
            for (int mf = 0; mf < 4; mf++)
#pragma unroll
                for (int nf = 0; nf < 4; nf++)
#pragma unroll
                    for (int e = 0; e < 4; e++) cacc[mf][nf][e] = 0.f;
        }

        const char* smB = sm + (s ? SM_B1 : SM_B0);
        // 6 limb passes: (ap,bp) with ap+bp <= 2
#pragma unroll
        for (int ap = 0; ap < 3; ap++) {
            uint4 af[4];
#pragma unroll
            for (int mf = 0; mf < 4; mf++)
                af[mf] = *(const uint4*)(sm + (wm * 4 + mf) * 24576 +
                                         ks * 1536 + ap * 512 + lane * 16);
#pragma unroll
            for (int bp = 0; bp < 3; bp++) {
                if (bp < 3 - ap) {
#pragma unroll
                    for (int nf = 0; nf < 4; nf++) {
                        uint2 bf = *(const uint2*)(smB + (wn * 4 + nf) * 768 +
                                                   bp * 256 + lane * 8);
#pragma unroll
                        for (int mf = 0; mf < 4; mf++)
                            mma16(cacc[mf][nf], af[mf], bf);
                    }
                }
            }
        }

        if (ks == 15) {
            // distance epilogue + per-thread running argmin (ascending codes)
            const float* e2t = g_e2 + nt * 128 + wn * 32;
#pragma unroll
            for (int nf = 0; nf < 4; nf++) {
                float2 e2v = *(const float2*)(e2t + nf * 8 + 2 * t);
                int code = nt * 128 + wn * 32 + nf * 8 + 2 * t;
#pragma unroll
                for (int mf = 0; mf < 4; mf++) {
#pragma unroll
                    for (int h = 0; h < 2; h++) {
                        int tk = mf * 2 + h;
                        float d0 = fmaf(-2.f, cacc[mf][nf][h * 2 + 0], e2v.x);
                        float d1 = fmaf(-2.f, cacc[mf][nf][h * 2 + 1], e2v.y);
                        if (d0 < minv[tk]) { minv[tk] = d0; mini[tk] = code; }
                        if (d1 < minv[tk]) { minv[tk] = d1; mini[tk] = code + 1; }
                    }
                }
            }
        }
        __syncthreads();
    }

    // merge: quad shfl over code-dim threads, then packed atomicMin
#pragma unroll
    for (int tk = 0; tk < 8; tk++) {
        uint32_t u = __float_as_uint(minv[tk]);
        u = (u & 0x80000000u) ? ~u : (u | 0x80000000u);
        unsigned long long p = ((unsigned long long)u << 32) | (unsigned)mini[tk];
        unsigned long long q;
        q = __shfl_xor_sync(0xffffffffu, p, 1); if (q < p) p = q;
        q = __shfl_xor_sync(0xffffffffu, p, 2); if (q < p) p = q;
        if (t == 0) {
            int mf = tk >> 1, h = tk & 1;
            atomicMin(&s_min[wm * 64 + mf * 16 + g + h * 8], p);
        }
    }
    __syncthreads();
    if (tid < 128) {
        int idx = (int)(s_min[tid] & 0xffffffffu);
        g_idx[m0 + tid]     = idx;
        out_idx_f[m0 + tid] = (float)idx;
    }
}

// ---------------- gather + loss (validated) ----------------
__global__ void k_gather(const float* __restrict__ X, const float* __restrict__ E,
                         float* __restrict__ outq) {
    __shared__ float red[256];
    const int tid = threadIdx.x;
    const long base = (long)blockIdx.x * 2048;
    float s = 0.f;
#pragma unroll
    for (int i = 0; i < 8; i++) {
        long e = base + i * 256 + tid;
        int  m = (int)(e >> 8);
        int  d = (int)(e & 255);
        float q = E[g_idx[m] * DIM + d];
        float x = X[e];
        float diff = q - x;
        outq[e] = x + diff;
        s = fmaf(diff, diff, s);
    }
    red[tid] = s;
    __syncthreads();
#pragma unroll
    for (int st = 128; st; st >>= 1) {
        if (tid < st) red[tid] += red[tid + st];
        __syncthreads();
    }
    if (tid == 0) g_part[blockIdx.x] = red[0];
}
__global__ void k_loss(float* __restrict__ loss_out) {
    __shared__ float red[256];
    const int tid = threadIdx.x;
    float s = 0.f;
    for (int i = tid; i < 4096; i += 256) s += g_part[i];
    red[tid] = s;
    __syncthreads();
#pragma unroll
    for (int st = 128; st; st >>= 1) {
        if (tid < st) red[tid] += red[tid + st];
        __syncthreads();
    }
    if (tid == 0) loss_out[0] = 2.0f * (red[0] / (float)QUANT_ELEMS);
}

// ---------------- launch ----------------
extern "C" void kernel_launch(void* const* d_in, const int* in_sizes, int n_in,
                              void* d_out, int out_size) {
    const float* X = (const float*)d_in[0];
    const float* E = (const float*)d_in[1];
    float* out = (float*)d_out;

    float* outq    = out;
    float* outloss = out + QUANT_ELEMS;
    float* outidx  = out + QUANT_ELEMS + 1;

    cudaFuncSetAttribute(k_main, cudaFuncAttributeMaxDynamicSharedMemorySize,
                         SM_TOTAL);

    k_prep_x<<<4096, 256>>>(X);
    k_prep_e<<<2048, 256>>>(E);
    k_e2    <<<N_CODE / 8, 256>>>(E);
    k_main  <<<N_TOK / 128, 256, SM_TOTAL>>>(outidx);
    k_gather<<<QUANT_ELEMS / 2048, 256>>>(X, E, outq);
    k_loss  <<<1, 256>>>(outloss);

    (void)in_sizes; (void)n_in; (void)out_size;
}